// round 14
// baseline (speedup 1.0000x reference)
#include <cuda_runtime.h>
#include <math.h>

#define H 1024
#define V 50257
#define L 12

#define ND1 6283               // kD1 blocks: ceil(V/8)
#define V4 12564               // full float4's in V (scalar tail = elem 50256)
#define NEG_BIG (-1e30f)       // finite sentinel: expf(NEG_BIG - x) == 0
#define KFIN_NT 1024
#define KFIN_NB 13             // 13*1024 = 13312 >= 12565 writes
#define KFIN_IT 7              // ceil(6283/1024)

// ---------------- scratch ----------------
__device__ __align__(16) float g_x[H];
__device__ __align__(16) float g_hh[H];
__device__ __align__(16) float g_hnew[H];
__device__ __align__(16) float g_logits[V];
__device__ float g_sm[ND1];
__device__ float g_ss[ND1];

__device__ __forceinline__ float warp_sum(float v)
{
    #pragma unroll
    for (int o = 16; o; o >>= 1) v += __shfl_xor_sync(0xffffffffu, v, o);
    return v;
}
__device__ __forceinline__ float warp_max(float v)
{
    #pragma unroll
    for (int o = 16; o; o >>= 1) v = fmaxf(v, __shfl_xor_sync(0xffffffffu, v, o));
    return v;
}

// ========== k1a: redundant attention -> x = relu(comb) ; hh = Whh@h0 =========
// grid 128 x 384 (12 warps)
__global__ __launch_bounds__(384) void k1a(
    const int*   __restrict__ tok,
    const float* __restrict__ hidden,
    const float* __restrict__ enc,
    const float* __restrict__ emb,
    const float* __restrict__ attn_W,
    const float* __restrict__ attn_b,
    const float* __restrict__ comb_W,
    const float* __restrict__ comb_b,
    const float* __restrict__ Whh,
    float* __restrict__ out_attnw)
{
    const int tid  = threadIdx.x;
    const int bid  = blockIdx.x;
    const int lane = tid & 31;
    const int wid  = tid >> 5;     // 0..11

    __shared__ float s_alog[L];
    __shared__ __align__(16) float sE[H];
    __shared__ __align__(16) float sHid[H];
    __shared__ __align__(16) float sAtt[H];

    const int token = tok[0];
    const float* __restrict__ erow = emb + (size_t)token * H;

    for (int i = tid; i < H; i += 384) { sE[i] = erow[i]; sHid[i] = hidden[i]; }
    __syncthreads();

    // attention logit: warp wid handles row wid (dot over [e;h], 2H)
    {
        const float4* __restrict__ wr = (const float4*)attn_W + wid * 512;
        const float4* e4 = (const float4*)sE;
        const float4* h4 = (const float4*)sHid;
        float s = 0.f;
        #pragma unroll
        for (int k = 0; k < 8; k++) {
            float4 wv = wr[k * 32 + lane];
            float4 xv = e4[k * 32 + lane];
            s = fmaf(wv.x, xv.x, fmaf(wv.y, xv.y, fmaf(wv.z, xv.z, fmaf(wv.w, xv.w, s))));
        }
        #pragma unroll
        for (int k = 0; k < 8; k++) {
            float4 wv = wr[256 + k * 32 + lane];
            float4 xv = h4[k * 32 + lane];
            s = fmaf(wv.x, xv.x, fmaf(wv.y, xv.y, fmaf(wv.z, xv.z, fmaf(wv.w, xv.w, s))));
        }
        s = warp_sum(s);
        if (lane == 0) s_alog[wid] = s + attn_b[wid];
    }
    __syncthreads();

    // redundant softmax
    float aw[L];
    {
        float mm = NEG_BIG;
        #pragma unroll
        for (int j = 0; j < L; j++) { aw[j] = s_alog[j]; mm = fmaxf(mm, aw[j]); }
        float sum = 0.f;
        #pragma unroll
        for (int j = 0; j < L; j++) { aw[j] = expf(aw[j] - mm); sum += aw[j]; }
        float inv = 1.f / sum;
        #pragma unroll
        for (int j = 0; j < L; j++) aw[j] *= inv;
    }
    if (bid == 0 && tid < L) out_attnw[tid] = aw[tid];

    for (int i = tid; i < H; i += 384) {
        float a = 0.f;
        #pragma unroll
        for (int j = 0; j < L; j++) a = fmaf(aw[j], enc[j * H + i], a);
        sAtt[i] = a;
    }
    __syncthreads();

    if (wid < 8) {
        // comb full-row dot: row = bid*8 + wid, over [sE ; sAtt]
        const int row = bid * 8 + wid;
        const float4* __restrict__ wr = (const float4*)comb_W + (size_t)row * 512;
        const float4* e4 = (const float4*)sE;
        const float4* a4 = (const float4*)sAtt;
        float s = 0.f;
        #pragma unroll
        for (int k = 0; k < 8; k++) {
            float4 wv = wr[k * 32 + lane];
            float4 xv = e4[k * 32 + lane];
            s = fmaf(wv.x, xv.x, fmaf(wv.y, xv.y, fmaf(wv.z, xv.z, fmaf(wv.w, xv.w, s))));
        }
        #pragma unroll
        for (int k = 0; k < 8; k++) {
            float4 wv = wr[256 + k * 32 + lane];
            float4 xv = a4[k * 32 + lane];
            s = fmaf(wv.x, xv.x, fmaf(wv.y, xv.y, fmaf(wv.z, xv.z, fmaf(wv.w, xv.w, s))));
        }
        s = warp_sum(s);
        if (lane == 0) g_x[row] = fmaxf(s + comb_b[row], 0.f);
    } else {
        // Whh full-row dots: 2 rows per warp
        const float4* h4 = (const float4*)sHid;
        #pragma unroll
        for (int r = 0; r < 2; r++) {
            const int row = bid * 8 + (wid - 8) * 2 + r;
            const float4* __restrict__ wr = (const float4*)Whh + (size_t)row * 256;
            float s = 0.f;
            #pragma unroll
            for (int k = 0; k < 8; k++) {
                float4 wv = wr[k * 32 + lane];
                float4 xv = h4[k * 32 + lane];
                s = fmaf(wv.x, xv.x, fmaf(wv.y, xv.y, fmaf(wv.z, xv.z, fmaf(wv.w, xv.w, s))));
            }
            s = warp_sum(s);
            if (lane == 0) g_hh[row] = s;
        }
    }
}

// ========== k1b: h_new = tanh(Wih@x + hh + bih + bhh)  (128 x 256) ============
__global__ __launch_bounds__(256) void k1b(
    const float* __restrict__ Wih,
    const float* __restrict__ bih,
    const float* __restrict__ bhh,
    float* __restrict__ out_h)
{
    __shared__ __align__(16) float4 sX[256];
    sX[threadIdx.x] = ((const float4*)g_x)[threadIdx.x];
    __syncthreads();

    const int wid = threadIdx.x >> 5, lane = threadIdx.x & 31;
    const int row = blockIdx.x * 8 + wid;
    const float4* __restrict__ wr = (const float4*)Wih + (size_t)row * 256;
    float s = 0.f;
    #pragma unroll
    for (int k = 0; k < 8; k++) {
        float4 wv = wr[k * 32 + lane];
        float4 xv = sX[k * 32 + lane];
        s = fmaf(wv.x, xv.x, fmaf(wv.y, xv.y, fmaf(wv.z, xv.z, fmaf(wv.w, xv.w, s))));
    }
    s = warp_sum(s);
    if (lane == 0) {
        float h = tanhf(s + g_hh[row] + bih[row] + bhh[row]);
        g_hnew[row] = h;
        out_h[row]  = h;
    }
}

// ========== kD1: logits GEMV (proven body) + block (m,s) =====================
__global__ __launch_bounds__(256) void kD1(const float* __restrict__ out_W,
                                           const float* __restrict__ out_b)
{
    __shared__ float4 s_h[256];
    __shared__ float red[8];
    s_h[threadIdx.x] = ((const float4*)g_hnew)[threadIdx.x];
    __syncthreads();

    const int wid = threadIdx.x >> 5, lane = threadIdx.x & 31;
    const int row = blockIdx.x * 8 + wid;

    float l = NEG_BIG;
    if (row < V) {
        const float4* __restrict__ w = (const float4*)(out_W + (size_t)row * H);
        float s = 0.f;
        #pragma unroll
        for (int k = 0; k < 8; k++) {
            float4 wv = w[k * 32 + lane];
            float4 hv = s_h[k * 32 + lane];
            s = fmaf(wv.x, hv.x, fmaf(wv.y, hv.y, fmaf(wv.z, hv.z, fmaf(wv.w, hv.w, s))));
        }
        s = warp_sum(s);
        l = s + out_b[row];
        if (lane == 0) g_logits[row] = l;
    }
    if (lane == 0) red[wid] = l;
    __syncthreads();
    if (wid == 0) {
        float v = (lane < 8) ? red[lane] : NEG_BIG;
        float m = warp_max(v);
        float e = (lane < 8) ? expf(v - m) : 0.f;
        float s = warp_sum(e);
        if (lane == 0) { g_sm[blockIdx.x] = m; g_ss[blockIdx.x] = s; }
    }
}

// ========== kFin: batched merge, 1024 thr (7 pairs/thread, no spill) ==========
__global__ __launch_bounds__(KFIN_NT) void kFin(float* __restrict__ out_logp)
{
    __shared__ float red[32];
    __shared__ float sh_M, sh_c;
    const int tid = threadIdx.x, lane = tid & 31, wid = tid >> 5;

    // ---- batched loads: 2*7 independent LDGs in flight ----
    float vm[KFIN_IT], vs[KFIN_IT];
    #pragma unroll
    for (int k = 0; k < KFIN_IT; k++) {
        const int idx = tid + k * KFIN_NT;
        const bool ok = idx < ND1;
        vm[k] = ok ? g_sm[idx] : NEG_BIG;
        vs[k] = ok ? g_ss[idx] : 0.f;
    }

    // ---- max (register tree + block reduce) ----
    float bm = vm[0];
    #pragma unroll
    for (int k = 1; k < KFIN_IT; k++) bm = fmaxf(bm, vm[k]);
    bm = warp_max(bm);
    if (lane == 0) red[wid] = bm;
    __syncthreads();
    if (wid == 0) {
        float m2 = warp_max(red[lane]);
        if (lane == 0) sh_M = m2;
    }
    __syncthreads();
    const float M = sh_M;

    // ---- scaled sum (independent expf) ----
    float bs = 0.f;
    #pragma unroll
    for (int k = 0; k < KFIN_IT; k++) bs += vs[k] * expf(vm[k] - M);
    bs = warp_sum(bs);
    __syncthreads();              // red[] reuse
    if (lane == 0) red[wid] = bs;
    __syncthreads();
    if (wid == 0) {
        float s2 = warp_sum(red[lane]);
        if (lane == 0) sh_c = M + logf(s2);
    }
    __syncthreads();
    const float c = sh_c;

    // ---- write logp ----
    const int idx = blockIdx.x * KFIN_NT + tid;      // 13*1024 = 13312 >= 12565
    if (idx < V4) {
        float4 v = ((const float4*)g_logits)[idx];
        v.x -= c; v.y -= c; v.z -= c; v.w -= c;
        ((float4*)out_logp)[idx] = v;
    } else if (idx == V4) {
        out_logp[V - 1] = g_logits[V - 1] - c;
    }
}

// ---------------- launcher ----------------------------------------------------
extern "C" void kernel_launch(void* const* d_in, const int* in_sizes, int n_in,
                              void* d_out, int out_size)
{
    const int*   tok    = (const int*)  d_in[0];
    const float* hidden = (const float*)d_in[1];
    const float* enc    = (const float*)d_in[2];
    const float* emb    = (const float*)d_in[3];
    const float* attn_W = (const float*)d_in[4];
    const float* attn_b = (const float*)d_in[5];
    const float* comb_W = (const float*)d_in[6];
    const float* comb_b = (const float*)d_in[7];
    const float* Wih    = (const float*)d_in[8];
    const float* Whh    = (const float*)d_in[9];
    const float* bih    = (const float*)d_in[10];
    const float* bhh    = (const float*)d_in[11];
    const float* out_W  = (const float*)d_in[12];
    const float* out_b  = (const float*)d_in[13];

    float* out = (float*)d_out;

    k1a<<<128, 384>>>(tok, hidden, enc, emb, attn_W, attn_b,
                      comb_W, comb_b, Whh, out + V + H);
    k1b<<<128, 256>>>(Wih, bih, bhh, out + V);
    kD1<<<ND1, 256>>>(out_W, out_b);
    kFin<<<KFIN_NB, KFIN_NT>>>(out);
}

// round 15
// speedup vs baseline: 1.0457x; 1.0457x over previous
#include <cuda_runtime.h>
#include <math.h>

#define H 1024
#define V 50257
#define L 12

#define ND1 6283               // kD1 blocks: ceil(V/8)
#define V4 12564               // full float4's in V (scalar tail = elem 50256)
#define NEG_BIG (-1e30f)       // finite sentinel: expf(NEG_BIG - x) == 0
#define KFIN_NT 1024
#define KFIN_NB 13             // 13*1024 = 13312 >= 12565 writes
#define KFIN_IT 7              // ceil(6283/1024)

// ---------------- scratch ----------------
__device__ __align__(16) float g_x[H];
__device__ __align__(16) float g_hh[H];
__device__ __align__(16) float g_hnew[H];
__device__ __align__(16) float g_logits[V];
__device__ float g_sm[ND1];
__device__ float g_ss[ND1];

__device__ __forceinline__ float warp_sum(float v)
{
    #pragma unroll
    for (int o = 16; o; o >>= 1) v += __shfl_xor_sync(0xffffffffu, v, o);
    return v;
}
__device__ __forceinline__ float warp_max(float v)
{
    #pragma unroll
    for (int o = 16; o; o >>= 1) v = fmaxf(v, __shfl_xor_sync(0xffffffffu, v, o));
    return v;
}

// ========== k1a: redundant attention -> x = relu(comb) ; hh = Whh@h0 =========
// grid 128 x 384 (12 warps)
__global__ __launch_bounds__(384) void k1a(
    const int*   __restrict__ tok,
    const float* __restrict__ hidden,
    const float* __restrict__ enc,
    const float* __restrict__ emb,
    const float* __restrict__ attn_W,
    const float* __restrict__ attn_b,
    const float* __restrict__ comb_W,
    const float* __restrict__ comb_b,
    const float* __restrict__ Whh,
    float* __restrict__ out_attnw)
{
#if defined(__CUDA_ARCH__) && __CUDA_ARCH__ >= 900
    cudaTriggerProgrammaticLaunchCompletion();   // let k1b launch + prefetch now
#endif
    const int tid  = threadIdx.x;
    const int bid  = blockIdx.x;
    const int lane = tid & 31;
    const int wid  = tid >> 5;     // 0..11

    __shared__ float s_alog[L];
    __shared__ __align__(16) float sE[H];
    __shared__ __align__(16) float sHid[H];
    __shared__ __align__(16) float sAtt[H];

    const int token = tok[0];
    const float* __restrict__ erow = emb + (size_t)token * H;

    for (int i = tid; i < H; i += 384) { sE[i] = erow[i]; sHid[i] = hidden[i]; }
    __syncthreads();

    // attention logit: warp wid handles row wid (dot over [e;h], 2H)
    {
        const float4* __restrict__ wr = (const float4*)attn_W + wid * 512;
        const float4* e4 = (const float4*)sE;
        const float4* h4 = (const float4*)sHid;
        float s = 0.f;
        #pragma unroll
        for (int k = 0; k < 8; k++) {
            float4 wv = wr[k * 32 + lane];
            float4 xv = e4[k * 32 + lane];
            s = fmaf(wv.x, xv.x, fmaf(wv.y, xv.y, fmaf(wv.z, xv.z, fmaf(wv.w, xv.w, s))));
        }
        #pragma unroll
        for (int k = 0; k < 8; k++) {
            float4 wv = wr[256 + k * 32 + lane];
            float4 xv = h4[k * 32 + lane];
            s = fmaf(wv.x, xv.x, fmaf(wv.y, xv.y, fmaf(wv.z, xv.z, fmaf(wv.w, xv.w, s))));
        }
        s = warp_sum(s);
        if (lane == 0) s_alog[wid] = s + attn_b[wid];
    }
    __syncthreads();

    // redundant softmax
    float aw[L];
    {
        float mm = NEG_BIG;
        #pragma unroll
        for (int j = 0; j < L; j++) { aw[j] = s_alog[j]; mm = fmaxf(mm, aw[j]); }
        float sum = 0.f;
        #pragma unroll
        for (int j = 0; j < L; j++) { aw[j] = expf(aw[j] - mm); sum += aw[j]; }
        float inv = 1.f / sum;
        #pragma unroll
        for (int j = 0; j < L; j++) aw[j] *= inv;
    }
    if (bid == 0 && tid < L) out_attnw[tid] = aw[tid];

    for (int i = tid; i < H; i += 384) {
        float a = 0.f;
        #pragma unroll
        for (int j = 0; j < L; j++) a = fmaf(aw[j], enc[j * H + i], a);
        sAtt[i] = a;
    }
    __syncthreads();

    if (wid < 8) {
        // comb full-row dot: row = bid*8 + wid, over [sE ; sAtt]
        const int row = bid * 8 + wid;
        const float4* __restrict__ wr = (const float4*)comb_W + (size_t)row * 512;
        const float4* e4 = (const float4*)sE;
        const float4* a4 = (const float4*)sAtt;
        float s = 0.f;
        #pragma unroll
        for (int k = 0; k < 8; k++) {
            float4 wv = wr[k * 32 + lane];
            float4 xv = e4[k * 32 + lane];
            s = fmaf(wv.x, xv.x, fmaf(wv.y, xv.y, fmaf(wv.z, xv.z, fmaf(wv.w, xv.w, s))));
        }
        #pragma unroll
        for (int k = 0; k < 8; k++) {
            float4 wv = wr[256 + k * 32 + lane];
            float4 xv = a4[k * 32 + lane];
            s = fmaf(wv.x, xv.x, fmaf(wv.y, xv.y, fmaf(wv.z, xv.z, fmaf(wv.w, xv.w, s))));
        }
        s = warp_sum(s);
        if (lane == 0) g_x[row] = fmaxf(s + comb_b[row], 0.f);
    } else {
        // Whh full-row dots: 2 rows per warp
        const float4* h4 = (const float4*)sHid;
        #pragma unroll
        for (int r = 0; r < 2; r++) {
            const int row = bid * 8 + (wid - 8) * 2 + r;
            const float4* __restrict__ wr = (const float4*)Whh + (size_t)row * 256;
            float s = 0.f;
            #pragma unroll
            for (int k = 0; k < 8; k++) {
                float4 wv = wr[k * 32 + lane];
                float4 xv = h4[k * 32 + lane];
                s = fmaf(wv.x, xv.x, fmaf(wv.y, xv.y, fmaf(wv.z, xv.z, fmaf(wv.w, xv.w, s))));
            }
            s = warp_sum(s);
            if (lane == 0) g_hh[row] = s;
        }
    }
}

// ========== k1b (PDL secondary): prefetch Wih row -> sync -> h_new ============
__global__ __launch_bounds__(256) void k1b(
    const float* __restrict__ Wih,
    const float* __restrict__ bih,
    const float* __restrict__ bhh,
    float* __restrict__ out_h)
{
#if defined(__CUDA_ARCH__) && __CUDA_ARCH__ >= 900
    cudaTriggerProgrammaticLaunchCompletion();   // let kD1 launch + prefetch now
#endif
    const int wid = threadIdx.x >> 5, lane = threadIdx.x & 31;
    const int row = blockIdx.x * 8 + wid;

    // dependence-free weight loads, issued before waiting on k1a
    const float4* __restrict__ wr = (const float4*)Wih + (size_t)row * 256;
    float4 wv[8];
    #pragma unroll
    for (int k = 0; k < 8; k++) wv[k] = wr[k * 32 + lane];

#if defined(__CUDA_ARCH__) && __CUDA_ARCH__ >= 900
    cudaGridDependencySynchronize();             // wait for k1a (g_x, g_hh)
#endif

    __shared__ __align__(16) float4 sX[256];
    sX[threadIdx.x] = ((const float4*)g_x)[threadIdx.x];
    __syncthreads();

    float s = 0.f;
    #pragma unroll
    for (int k = 0; k < 8; k++) {
        float4 xv = sX[k * 32 + lane];
        s = fmaf(wv[k].x, xv.x, fmaf(wv[k].y, xv.y, fmaf(wv[k].z, xv.z, fmaf(wv[k].w, xv.w, s))));
    }
    s = warp_sum(s);
    if (lane == 0) {
        float h = tanhf(s + g_hh[row] + bih[row] + bhh[row]);
        g_hnew[row] = h;
        out_h[row]  = h;
    }
}

// ========== kD1 (PDL secondary): prefetch out_W row -> sync -> logits =========
__global__ __launch_bounds__(256) void kD1(const float* __restrict__ out_W,
                                           const float* __restrict__ out_b)
{
    const int wid = threadIdx.x >> 5, lane = threadIdx.x & 31;
    const int row = blockIdx.x * 8 + wid;

    // dependence-free weight loads (the 206MB stream) before waiting on k1b
    float4 wv[8];
    if (row < V) {
        const float4* __restrict__ w = (const float4*)(out_W + (size_t)row * H);
        #pragma unroll
        for (int k = 0; k < 8; k++) wv[k] = w[k * 32 + lane];
    }

#if defined(__CUDA_ARCH__) && __CUDA_ARCH__ >= 900
    cudaGridDependencySynchronize();             // wait for k1b (g_hnew)
#endif

    __shared__ float4 s_h[256];
    __shared__ float red[8];
    s_h[threadIdx.x] = ((const float4*)g_hnew)[threadIdx.x];
    __syncthreads();

    float l = NEG_BIG;
    if (row < V) {
        float s = 0.f;
        #pragma unroll
        for (int k = 0; k < 8; k++) {
            float4 hv = s_h[k * 32 + lane];
            s = fmaf(wv[k].x, hv.x, fmaf(wv[k].y, hv.y, fmaf(wv[k].z, hv.z, fmaf(wv[k].w, hv.w, s))));
        }
        s = warp_sum(s);
        l = s + out_b[row];
        if (lane == 0) g_logits[row] = l;
    }
    if (lane == 0) red[wid] = l;
    __syncthreads();
    if (wid == 0) {
        float v = (lane < 8) ? red[lane] : NEG_BIG;
        float m = warp_max(v);
        float e = (lane < 8) ? expf(v - m) : 0.f;
        float s = warp_sum(e);
        if (lane == 0) { g_sm[blockIdx.x] = m; g_ss[blockIdx.x] = s; }
    }
}

// ========== kFin: batched merge, 1024 thr (7 pairs/thread) ====================
__global__ __launch_bounds__(KFIN_NT) void kFin(float* __restrict__ out_logp)
{
    __shared__ float red[32];
    __shared__ float sh_M, sh_c;
    const int tid = threadIdx.x, lane = tid & 31, wid = tid >> 5;

    float vm[KFIN_IT], vs[KFIN_IT];
    #pragma unroll
    for (int k = 0; k < KFIN_IT; k++) {
        const int idx = tid + k * KFIN_NT;
        const bool ok = idx < ND1;
        vm[k] = ok ? g_sm[idx] : NEG_BIG;
        vs[k] = ok ? g_ss[idx] : 0.f;
    }

    float bm = vm[0];
    #pragma unroll
    for (int k = 1; k < KFIN_IT; k++) bm = fmaxf(bm, vm[k]);
    bm = warp_max(bm);
    if (lane == 0) red[wid] = bm;
    __syncthreads();
    if (wid == 0) {
        float m2 = warp_max(red[lane]);
        if (lane == 0) sh_M = m2;
    }
    __syncthreads();
    const float M = sh_M;

    float bs = 0.f;
    #pragma unroll
    for (int k = 0; k < KFIN_IT; k++) bs += vs[k] * expf(vm[k] - M);
    bs = warp_sum(bs);
    __syncthreads();
    if (lane == 0) red[wid] = bs;
    __syncthreads();
    if (wid == 0) {
        float s2 = warp_sum(red[lane]);
        if (lane == 0) sh_c = M + logf(s2);
    }
    __syncthreads();
    const float c = sh_c;

    const int idx = blockIdx.x * KFIN_NT + tid;      // 13*1024 >= 12565
    if (idx < V4) {
        float4 v = ((const float4*)g_logits)[idx];
        v.x -= c; v.y -= c; v.z -= c; v.w -= c;
        ((float4*)out_logp)[idx] = v;
    } else if (idx == V4) {
        out_logp[V - 1] = g_logits[V - 1] - c;
    }
}

// ---------------- launcher ----------------------------------------------------
extern "C" void kernel_launch(void* const* d_in, const int* in_sizes, int n_in,
                              void* d_out, int out_size)
{
    const int*   tok    = (const int*)  d_in[0];
    const float* hidden = (const float*)d_in[1];
    const float* enc    = (const float*)d_in[2];
    const float* emb    = (const float*)d_in[3];
    const float* attn_W = (const float*)d_in[4];
    const float* attn_b = (const float*)d_in[5];
    const float* comb_W = (const float*)d_in[6];
    const float* comb_b = (const float*)d_in[7];
    const float* Wih    = (const float*)d_in[8];
    const float* Whh    = (const float*)d_in[9];
    const float* bih    = (const float*)d_in[10];
    const float* bhh    = (const float*)d_in[11];
    const float* out_W  = (const float*)d_in[12];
    const float* out_b  = (const float*)d_in[13];

    float* out = (float*)d_out;

    // k1a: normal launch
    k1a<<<128, 384>>>(tok, hidden, enc, emb, attn_W, attn_b,
                      comb_W, comb_b, Whh, out + V + H);

    // k1b: PDL secondary of k1a
    {
        cudaLaunchConfig_t cfg = {};
        cfg.gridDim  = dim3(128);
        cfg.blockDim = dim3(256);
        cudaLaunchAttribute at[1];
        at[0].id = cudaLaunchAttributeProgrammaticStreamSerialization;
        at[0].val.programmaticStreamSerializationAllowed = 1;
        cfg.attrs = at;
        cfg.numAttrs = 1;
        cudaLaunchKernelEx(&cfg, k1b, Wih, bih, bhh, (float*)(out + V));
    }

    // kD1: PDL secondary of k1b
    {
        cudaLaunchConfig_t cfg = {};
        cfg.gridDim  = dim3(ND1);
        cfg.blockDim = dim3(256);
        cudaLaunchAttribute at[1];
        at[0].id = cudaLaunchAttributeProgrammaticStreamSerialization;
        at[0].val.programmaticStreamSerializationAllowed = 1;
        cfg.attrs = at;
        cfg.numAttrs = 1;
        cudaLaunchKernelEx(&cfg, kD1, out_W, out_b);
    }

    // kFin: normal launch
    kFin<<<KFIN_NB, KFIN_NT>>>(out);
}